// round 12
// baseline (speedup 1.0000x reference)
#include <cuda_runtime.h>
#include <math.h>

#define ALPHA 0.2f
#define BN_SCALE 0.99950037f   // 1/sqrt(1 + 1e-3)

typedef unsigned long long u64;

// ---------------- packed f32x2 helpers ------------------------------------
__device__ __forceinline__ u64 pack2b(float v) {
    u64 r; asm("mov.b64 %0, {%1, %1};" : "=l"(r) : "f"(v)); return r;
}
__device__ __forceinline__ u64 pack2f(float lo, float hi) {
    u64 r; asm("mov.b64 %0, {%1, %2};" : "=l"(r) : "f"(lo), "f"(hi)); return r;
}
__device__ __forceinline__ float2 unpack2(u64 v) {
    float2 r; asm("mov.b64 {%0, %1}, %2;" : "=f"(r.x), "=f"(r.y) : "l"(v));
    return r;
}
__device__ __forceinline__ void ffma2(u64& d, u64 a, u64 b) {
    asm("fma.rn.f32x2 %0, %1, %2, %0;" : "+l"(d) : "l"(a), "l"(b));
}
__device__ __forceinline__ float lrelu(float x) {
    return x > 0.f ? x : ALPHA * x;
}
__device__ __forceinline__ float f4c(const float4& v, int s) {
    return s == 0 ? v.x : s == 1 ? v.y : s == 2 ? v.z : v.w;
}

// ---------------- scratch (device globals; no allocation) ----------------
__device__ float g_a1[4 * 256 * 256 * 32];
__device__ float g_a2[4 * 128 * 128 * 32];
__device__ float g_a3[4 * 64 * 64 * 32];
__device__ float g_f0[4 * 64 * 64 * 32];
__device__ float g_f1[4 * 64 * 64 * 32];
__device__ float g_disp[4 * 64 * 64 * 2];

// ============ stage 1: conv3x3 Cin=2 + BN + LReLU + pool, 8px/thread ======
__global__ __launch_bounds__(128) void k_conv0(const float* __restrict__ fixed,
                                               const float* __restrict__ moving,
                                               const float* __restrict__ w0) {
    __shared__ float sw[576];                 // (3,3,2,32)
    int t = threadIdx.x;
    for (int i = t; i < 576; i += 128) sw[i] = w0[i];
    __syncthreads();

    int lin = blockIdx.x * 128 + t;           // 4*256*128*4 = 524288
    int og = lin & 3;
    int idx = lin >> 2;
    int pp = idx & 127;                       // 128 cell-pairs per row
    int py = (idx >> 7) & 255;
    int b = idx >> 15;
    int cx0 = 4 * pp, cy0 = 2 * py;

    u64 acc[8][4];
#pragma unroll
    for (int i = 0; i < 8; i++)
#pragma unroll
        for (int p = 0; p < 4; p++) acc[i][p] = 0ULL;

#pragma unroll
    for (int iy = 0; iy < 4; iy++) {
        int gy = cy0 - 1 + iy;
        bool rowok = (unsigned)gy < 512u;
        u64 pf[6], pm[6];
#pragma unroll
        for (int c = 0; c < 6; c++) {
            int gx = cx0 - 1 + c;
            bool ok = rowok && (unsigned)gx < 512u;
            int off = (b << 18) + (gy << 9) + gx;
            pf[c] = ok ? pack2b(fixed[off]) : 0ULL;
            pm[c] = ok ? pack2b(moving[off]) : 0ULL;
        }
#pragma unroll
        for (int r = 0; r < 2; r++) {
            int ky = iy - r;
            if (ky < 0 || ky > 2) continue;
#pragma unroll
            for (int kx = 0; kx < 3; kx++) {
                const ulonglong2* wf = reinterpret_cast<const ulonglong2*>(
                    sw + (ky * 3 + kx) * 64 + og * 8);
                const ulonglong2* wm = reinterpret_cast<const ulonglong2*>(
                    sw + (ky * 3 + kx) * 64 + 32 + og * 8);
                ulonglong2 wfa = wf[0], wfb = wf[1];
                ulonglong2 wma = wm[0], wmb = wm[1];
#pragma unroll
                for (int c = 0; c < 4; c++) {
                    u64 vf = pf[c + kx], vm = pm[c + kx];
                    ffma2(acc[r * 4 + c][0], vf, wfa.x);
                    ffma2(acc[r * 4 + c][1], vf, wfa.y);
                    ffma2(acc[r * 4 + c][2], vf, wfb.x);
                    ffma2(acc[r * 4 + c][3], vf, wfb.y);
                    ffma2(acc[r * 4 + c][0], vm, wma.x);
                    ffma2(acc[r * 4 + c][1], vm, wma.y);
                    ffma2(acc[r * 4 + c][2], vm, wmb.x);
                    ffma2(acc[r * 4 + c][3], vm, wmb.y);
                }
            }
        }
    }

#pragma unroll
    for (int cc = 0; cc < 2; cc++) {
        u64 resv[4];
#pragma unroll
        for (int p = 0; p < 4; p++) {
            float2 f00 = unpack2(acc[2 * cc][p]);
            float2 f01 = unpack2(acc[2 * cc + 1][p]);
            float2 f10 = unpack2(acc[4 + 2 * cc][p]);
            float2 f11 = unpack2(acc[4 + 2 * cc + 1][p]);
            float lo = lrelu(f00.x * BN_SCALE) + lrelu(f01.x * BN_SCALE) +
                       lrelu(f10.x * BN_SCALE) + lrelu(f11.x * BN_SCALE);
            float hi = lrelu(f00.y * BN_SCALE) + lrelu(f01.y * BN_SCALE) +
                       lrelu(f10.y * BN_SCALE) + lrelu(f11.y * BN_SCALE);
            resv[p] = pack2f(lo * 0.25f, hi * 0.25f);
        }
        int px = 2 * pp + cc;
        ulonglong2* op = reinterpret_cast<ulonglong2*>(
            g_a1 + ((size_t)(b * 256 + py) * 256 + px) * 32 + og * 8);
        op[0] = make_ulonglong2(resv[0], resv[1]);
        op[1] = make_ulonglong2(resv[2], resv[3]);
    }
}

// ============ conv3x3 32->32 + BN + LReLU + pool, 8px x 4oc /thread =======
// og of 8 (4 oc per thread): 1 LDS.128 weight feeds 8 FFMA2 via 4-px block.
template <int HIN>
__device__ __forceinline__ void convpool_body(const float* __restrict__ in,
                                              float* __restrict__ out,
                                              const float* __restrict__ w) {
    __shared__ float sw[9216];                // (3,3,32,32)
    int t = threadIdx.x;
    for (int i = t; i < 9216; i += 128) sw[i] = w[i];
    __syncthreads();

    const int HOUT = HIN / 2;
    const int PPW = HOUT / 2;
    int lin = blockIdx.x * 128 + t;           // 4*HOUT*PPW*8 threads
    int og = lin & 7;                         // 4 oc per thread
    int idx = lin >> 3;
    int pp = idx % PPW;
    int tmp = idx / PPW;
    int py = tmp % HOUT;
    int b = tmp / HOUT;
    int cx0 = 4 * pp, cy0 = 2 * py;

    u64 acc[8][2];
#pragma unroll
    for (int i = 0; i < 8; i++) { acc[i][0] = 0ULL; acc[i][1] = 0ULL; }

    for (int ic4 = 0; ic4 < 8; ic4++) {
#pragma unroll
        for (int iy = 0; iy < 4; iy++) {
            int gy = cy0 - 1 + iy;
            bool rowok = (unsigned)gy < (unsigned)HIN;
            float4 rowv[6];
#pragma unroll
            for (int c = 0; c < 6; c++) {
                int gx = cx0 - 1 + c;
                if (rowok && (unsigned)gx < (unsigned)HIN)
                    rowv[c] = reinterpret_cast<const float4*>(
                        in + ((size_t)(b * HIN + gy) * HIN + gx) * 32)[ic4];
                else
                    rowv[c] = make_float4(0.f, 0.f, 0.f, 0.f);
            }
#pragma unroll
            for (int s = 0; s < 4; s++) {
                u64 pu[6];
#pragma unroll
                for (int c = 0; c < 6; c++) pu[c] = pack2b(f4c(rowv[c], s));
#pragma unroll
                for (int r = 0; r < 2; r++) {
                    int ky = iy - r;
                    if (ky < 0 || ky > 2) continue;
#pragma unroll
                    for (int kx = 0; kx < 3; kx++) {
                        const ulonglong2* wp =
                            reinterpret_cast<const ulonglong2*>(
                                sw + (ky * 3 + kx) * 1024 + (ic4 * 4 + s) * 32 +
                                og * 4);
                        ulonglong2 wv = wp[0];
#pragma unroll
                        for (int c = 0; c < 4; c++) {
                            u64 v = pu[c + kx];
                            ffma2(acc[r * 4 + c][0], v, wv.x);
                            ffma2(acc[r * 4 + c][1], v, wv.y);
                        }
                    }
                }
            }
        }
    }

#pragma unroll
    for (int cc = 0; cc < 2; cc++) {
        u64 resv[2];
#pragma unroll
        for (int p = 0; p < 2; p++) {
            float2 f00 = unpack2(acc[2 * cc][p]);
            float2 f01 = unpack2(acc[2 * cc + 1][p]);
            float2 f10 = unpack2(acc[4 + 2 * cc][p]);
            float2 f11 = unpack2(acc[4 + 2 * cc + 1][p]);
            float lo = lrelu(f00.x * BN_SCALE) + lrelu(f01.x * BN_SCALE) +
                       lrelu(f10.x * BN_SCALE) + lrelu(f11.x * BN_SCALE);
            float hi = lrelu(f00.y * BN_SCALE) + lrelu(f01.y * BN_SCALE) +
                       lrelu(f10.y * BN_SCALE) + lrelu(f11.y * BN_SCALE);
            resv[p] = pack2f(lo * 0.25f, hi * 0.25f);
        }
        int px = 2 * pp + cc;
        ulonglong2* op = reinterpret_cast<ulonglong2*>(
            out + ((size_t)(b * HOUT + py) * HOUT + px) * 32 + og * 4);
        op[0] = make_ulonglong2(resv[0], resv[1]);
    }
}

__global__ __launch_bounds__(128) void k_stage2(const float* __restrict__ w) {
    convpool_body<256>(g_a1, g_a2, w);
}
__global__ __launch_bounds__(128) void k_stage3(const float* __restrict__ w) {
    convpool_body<128>(g_a2, g_a3, w);
}

// ============ conv3x3 32->32 + BN + LReLU (64x64), 2px x 4oc /thread ======
__device__ __forceinline__ void fconv_body(const float* __restrict__ in,
                                           float* __restrict__ out,
                                           const float* __restrict__ w) {
    __shared__ float sw[9216];
    int t = threadIdx.x;
    for (int i = t; i < 9216; i += 128) sw[i] = w[i];
    __syncthreads();

    int lin = blockIdx.x * 128 + t;           // 4*64*32*8 = 65536
    int og = lin & 7;                         // 4 oc each
    int idx = lin >> 3;
    int xb = idx & 31;                        // 32 pixel-pairs per row
    int y = (idx >> 5) & 63;
    int b = idx >> 11;
    int x0 = 2 * xb;

    u64 acc[2][2];
    acc[0][0] = acc[0][1] = acc[1][0] = acc[1][1] = 0ULL;

    for (int ic4 = 0; ic4 < 8; ic4++) {
#pragma unroll
        for (int ky = 0; ky < 3; ky++) {
            int gy = y + ky - 1;
            bool rowok = (unsigned)gy < 64u;
            float4 rowv[4];
#pragma unroll
            for (int c = 0; c < 4; c++) {
                int gx = x0 - 1 + c;
                if (rowok && (unsigned)gx < 64u)
                    rowv[c] = reinterpret_cast<const float4*>(
                        in + ((size_t)((b * 64 + gy) * 64 + gx)) * 32)[ic4];
                else
                    rowv[c] = make_float4(0.f, 0.f, 0.f, 0.f);
            }
#pragma unroll
            for (int s = 0; s < 4; s++) {
                u64 pu[4];
#pragma unroll
                for (int c = 0; c < 4; c++) pu[c] = pack2b(f4c(rowv[c], s));
#pragma unroll
                for (int kx = 0; kx < 3; kx++) {
                    const ulonglong2* wp = reinterpret_cast<const ulonglong2*>(
                        sw + (ky * 3 + kx) * 1024 + (ic4 * 4 + s) * 32 + og * 4);
                    ulonglong2 wv = wp[0];
#pragma unroll
                    for (int c = 0; c < 2; c++) {
                        u64 v = pu[c + kx];
                        ffma2(acc[c][0], v, wv.x);
                        ffma2(acc[c][1], v, wv.y);
                    }
                }
            }
        }
    }

#pragma unroll
    for (int c = 0; c < 2; c++) {
        float2 f0 = unpack2(acc[c][0]);
        float2 f1 = unpack2(acc[c][1]);
        float4 r;
        r.x = lrelu(f0.x * BN_SCALE);
        r.y = lrelu(f0.y * BN_SCALE);
        r.z = lrelu(f1.x * BN_SCALE);
        r.w = lrelu(f1.y * BN_SCALE);
        int pxl = (b * 64 + y) * 64 + x0 + c;
        reinterpret_cast<float4*>(out + (size_t)pxl * 32 + og * 4)[0] = r;
    }
}

__global__ __launch_bounds__(128) void k_fconv0(const float* __restrict__ w) {
    fconv_body(g_a3, g_f0, w);
}
__global__ __launch_bounds__(128) void k_fconv1(const float* __restrict__ w) {
    fconv_body(g_f0, g_f1, w);
}

// ---------------- pointwise pw0 (LReLU) then pw1 -> disp ------------------
__global__ __launch_bounds__(128) void k_pw(const float* __restrict__ pw0,
                                            const float* __restrict__ pw1) {
    __shared__ float s0[1024];
    __shared__ float s1[64];
    int t = threadIdx.x;
    for (int i = t; i < 1024; i += 128) s0[i] = pw0[i];
    if (t < 64) s1[t] = pw1[t];
    __syncthreads();

    int idx = blockIdx.x * 128 + t;           // 16384
    const float4* ip = reinterpret_cast<const float4*>(g_f1 + (size_t)idx * 32);
    float xv[32];
#pragma unroll
    for (int i = 0; i < 8; i++) {
        float4 v = ip[i];
        xv[i * 4 + 0] = v.x; xv[i * 4 + 1] = v.y;
        xv[i * 4 + 2] = v.z; xv[i * 4 + 3] = v.w;
    }
    float d0 = 0.f, d1 = 0.f;
#pragma unroll
    for (int oc = 0; oc < 32; oc++) {
        float a = 0.f;
#pragma unroll
        for (int ic = 0; ic < 32; ic++) a += xv[ic] * s0[ic * 32 + oc];
        a = lrelu(a);
        d0 += a * s1[oc * 2 + 0];
        d1 += a * s1[oc * 2 + 1];
    }
    g_disp[idx * 2 + 0] = d0;
    g_disp[idx * 2 + 1] = d1;
}

// ---------------- B-spline upsample + bilinear warp + outputs -------------
__global__ __launch_bounds__(256) void k_warp(const float* __restrict__ moving,
                                              float* __restrict__ out) {
    int idx = blockIdx.x * 256 + threadIdx.x; // 4*512*512
    int b = idx >> 18;
    int rem = idx & 262143;
    int h = rem >> 9, w = rem & 511;

    float xv = fminf(w * 0.125f, 63.f);
    float yv = fminf(h * 0.125f, 63.f);
    int ii = (int)xv;
    int jj = (int)yv;
    float u = xv * 0.015625f;
    float v = yv * 0.015625f;

    float u2 = u * u, u3 = u2 * u;
    float v2 = v * v, v3 = v2 * v;
    float Bu[4] = { -u3 + 3.f * u2 - 3.f * u + 1.f,
                     3.f * u3 - 6.f * u2 + 4.f,
                    -3.f * u3 + 3.f * u2 + 3.f * u + 1.f,
                     u3 };
    float Bv[4] = { -v3 + 3.f * v2 - 3.f * v + 1.f,
                     3.f * v3 - 6.f * v2 + 4.f,
                    -3.f * v3 + 3.f * v2 + 3.f * v + 1.f,
                     v3 };

    const float2* dp = reinterpret_cast<const float2*>(g_disp);
    float i0 = 0.f, i1 = 0.f;
#pragma unroll
    for (int m = 0; m < 4; m++) {
        int ry = jj + m - 1;
        if ((unsigned)ry >= 64u) continue;
        float s0 = 0.f, s1 = 0.f;
#pragma unroll
        for (int n = 0; n < 4; n++) {
            int rx = ii + n - 1;
            if ((unsigned)rx >= 64u) continue;
            float2 d = dp[(b * 64 + ry) * 64 + rx];
            s0 += Bv[n] * d.x;
            s1 += Bv[n] * d.y;
        }
        i0 += Bu[m] * s0;
        i1 += Bu[m] * s1;
    }

    float wxf = i0 + (float)w;
    float wyf = i1 + (float)h;

    float fx = floorf(wxf);
    float x0 = fminf(fmaxf(fx, 0.f), 511.f);
    float x1 = fminf(fmaxf(fx + 1.f, 0.f), 511.f);
    float fy = floorf(wyf);
    float y0 = fminf(fmaxf(fy, 0.f), 511.f);
    float y1 = fminf(fmaxf(fy + 1.f, 0.f), 511.f);
    int x0i = (int)x0, x1i = (int)x1, y0i = (int)y0, y1i = (int)y1;

    const float* im = moving + ((size_t)b << 18);
    float Q1 = im[y0i * 512 + x0i];
    float Q2 = im[y1i * 512 + x0i];
    float Q3 = im[y0i * 512 + x1i];
    float Q4 = im[y1i * 512 + x1i];

    float invx = 1.f / (x1 - x0 + 1e-5f);
    float wxr = (x1 - wxf) * invx;
    float wxl = (wxf - x0) * invx;
    float R1 = wxr * Q1 + wxl * Q3;
    float R2 = wxr * Q2 + wxl * Q4;
    float invy = 1.f / (y1 - y0 + 1e-5f);
    float res = (y1 - wyf) * invy * R1 + (wyf - y0) * invy * R2;

    out[(b << 18) + (h << 9) + w] = res;
    const int WOFF = 4 * 512 * 512;
    out[WOFF + ((b * 2 + 0) << 18) + (h << 9) + w] = wxf;
    out[WOFF + ((b * 2 + 1) << 18) + (h << 9) + w] = wyf;
}

// ---------------- launch ---------------------------------------------------
extern "C" void kernel_launch(void* const* d_in, const int* in_sizes, int n_in,
                              void* d_out, int out_size) {
    const float* fixed  = (const float*)d_in[0];
    const float* moving = (const float*)d_in[1];
    const float* w0  = (const float*)d_in[2];
    const float* w1  = (const float*)d_in[3];
    const float* w2  = (const float*)d_in[4];
    const float* fw0 = (const float*)d_in[5];
    const float* fw1 = (const float*)d_in[6];
    const float* pw0 = (const float*)d_in[7];
    const float* pw1 = (const float*)d_in[8];
    float* out = (float*)d_out;

    k_conv0<<<4096, 128>>>(fixed, moving, w0);   // 512 -> 256, 8px x 8oc
    k_stage2<<<2048, 128>>>(w1);                 // 256 -> 128, 8px x 4oc
    k_stage3<<<512, 128>>>(w2);                  // 128 -> 64,  8px x 4oc
    k_fconv0<<<512, 128>>>(fw0);                 // 64x64, 2px x 4oc
    k_fconv1<<<512, 128>>>(fw1);                 // 64x64, 2px x 4oc
    k_pw<<<128, 128>>>(pw0, pw1);                // pointwise -> disp
    k_warp<<<4096, 256>>>(moving, out);          // upsample + warp
}

// round 13
// speedup vs baseline: 1.0578x; 1.0578x over previous
#include <cuda_runtime.h>
#include <math.h>

#define ALPHA 0.2f
#define BN_SCALE 0.99950037f   // 1/sqrt(1 + 1e-3)

typedef unsigned long long u64;

// ---------------- packed f32x2 helpers ------------------------------------
__device__ __forceinline__ u64 pack2b(float v) {
    u64 r; asm("mov.b64 %0, {%1, %1};" : "=l"(r) : "f"(v)); return r;
}
__device__ __forceinline__ u64 pack2f(float lo, float hi) {
    u64 r; asm("mov.b64 %0, {%1, %2};" : "=l"(r) : "f"(lo), "f"(hi)); return r;
}
__device__ __forceinline__ float2 unpack2(u64 v) {
    float2 r; asm("mov.b64 {%0, %1}, %2;" : "=f"(r.x), "=f"(r.y) : "l"(v));
    return r;
}
__device__ __forceinline__ void ffma2(u64& d, u64 a, u64 b) {
    asm("fma.rn.f32x2 %0, %1, %2, %0;" : "+l"(d) : "l"(a), "l"(b));
}
__device__ __forceinline__ u64 add2(u64 a, u64 b) {
    u64 r; asm("add.rn.f32x2 %0, %1, %2;" : "=l"(r) : "l"(a), "l"(b));
    return r;
}
__device__ __forceinline__ float lrelu(float x) {
    return x > 0.f ? x : ALPHA * x;
}
__device__ __forceinline__ float f4c(const float4& v, int s) {
    return s == 0 ? v.x : s == 1 ? v.y : s == 2 ? v.z : v.w;
}

// ---------------- scratch (device globals; no allocation) ----------------
__device__ float g_a1[4 * 256 * 256 * 32];
__device__ float g_a2[4 * 128 * 128 * 32];
__device__ float g_a3[4 * 64 * 64 * 32];
__device__ float g_f0[4 * 64 * 64 * 32];
__device__ float g_f1[4 * 64 * 64 * 32];
__device__ float g_disp[4 * 64 * 64 * 2];

// ============ stage 1: conv3x3 Cin=2 + BN + LReLU + pool, 8px x 8oc =======
__global__ __launch_bounds__(128) void k_conv0(const float* __restrict__ fixed,
                                               const float* __restrict__ moving,
                                               const float* __restrict__ w0) {
    __shared__ float sw[576];                 // (3,3,2,32)
    int t = threadIdx.x;
    for (int i = t; i < 576; i += 128) sw[i] = w0[i];
    __syncthreads();

    int lin = blockIdx.x * 128 + t;           // 4*256*128*4 = 524288
    int og = lin & 3;
    int idx = lin >> 2;
    int pp = idx & 127;
    int py = (idx >> 7) & 255;
    int b = idx >> 15;
    int cx0 = 4 * pp, cy0 = 2 * py;

    u64 acc[8][4];
#pragma unroll
    for (int i = 0; i < 8; i++)
#pragma unroll
        for (int p = 0; p < 4; p++) acc[i][p] = 0ULL;

#pragma unroll
    for (int iy = 0; iy < 4; iy++) {
        int gy = cy0 - 1 + iy;
        bool rowok = (unsigned)gy < 512u;
        u64 pf[6], pm[6];
#pragma unroll
        for (int c = 0; c < 6; c++) {
            int gx = cx0 - 1 + c;
            bool ok = rowok && (unsigned)gx < 512u;
            int off = (b << 18) + (gy << 9) + gx;
            pf[c] = ok ? pack2b(fixed[off]) : 0ULL;
            pm[c] = ok ? pack2b(moving[off]) : 0ULL;
        }
#pragma unroll
        for (int r = 0; r < 2; r++) {
            int ky = iy - r;
            if (ky < 0 || ky > 2) continue;
#pragma unroll
            for (int kx = 0; kx < 3; kx++) {
                const ulonglong2* wf = reinterpret_cast<const ulonglong2*>(
                    sw + (ky * 3 + kx) * 64 + og * 8);
                const ulonglong2* wm = reinterpret_cast<const ulonglong2*>(
                    sw + (ky * 3 + kx) * 64 + 32 + og * 8);
                ulonglong2 wfa = wf[0], wfb = wf[1];
                ulonglong2 wma = wm[0], wmb = wm[1];
#pragma unroll
                for (int c = 0; c < 4; c++) {
                    u64 vf = pf[c + kx], vm = pm[c + kx];
                    ffma2(acc[r * 4 + c][0], vf, wfa.x);
                    ffma2(acc[r * 4 + c][1], vf, wfa.y);
                    ffma2(acc[r * 4 + c][2], vf, wfb.x);
                    ffma2(acc[r * 4 + c][3], vf, wfb.y);
                    ffma2(acc[r * 4 + c][0], vm, wma.x);
                    ffma2(acc[r * 4 + c][1], vm, wma.y);
                    ffma2(acc[r * 4 + c][2], vm, wmb.x);
                    ffma2(acc[r * 4 + c][3], vm, wmb.y);
                }
            }
        }
    }

#pragma unroll
    for (int cc = 0; cc < 2; cc++) {
        u64 resv[4];
#pragma unroll
        for (int p = 0; p < 4; p++) {
            float2 f00 = unpack2(acc[2 * cc][p]);
            float2 f01 = unpack2(acc[2 * cc + 1][p]);
            float2 f10 = unpack2(acc[4 + 2 * cc][p]);
            float2 f11 = unpack2(acc[4 + 2 * cc + 1][p]);
            float lo = lrelu(f00.x * BN_SCALE) + lrelu(f01.x * BN_SCALE) +
                       lrelu(f10.x * BN_SCALE) + lrelu(f11.x * BN_SCALE);
            float hi = lrelu(f00.y * BN_SCALE) + lrelu(f01.y * BN_SCALE) +
                       lrelu(f10.y * BN_SCALE) + lrelu(f11.y * BN_SCALE);
            resv[p] = pack2f(lo * 0.25f, hi * 0.25f);
        }
        int px = 2 * pp + cc;
        ulonglong2* op = reinterpret_cast<ulonglong2*>(
            g_a1 + ((size_t)(b * 256 + py) * 256 + px) * 32 + og * 8);
        op[0] = make_ulonglong2(resv[0], resv[1]);
        op[1] = make_ulonglong2(resv[2], resv[3]);
    }
}

// ============ conv3x3 32->32 + BN + LReLU + pool, 8px x 8oc (opt icsplit) =
template <int HIN, int ICS>
__device__ __forceinline__ void convpool_body(const float* __restrict__ in,
                                              float* __restrict__ out,
                                              const float* __restrict__ w) {
    __shared__ float sw[9216];                // (3,3,32,32)
    int t = threadIdx.x;
    for (int i = t; i < 9216; i += 128) sw[i] = w[i];
    __syncthreads();

    const int HOUT = HIN / 2;
    const int PPW = HOUT / 2;
    int lin = blockIdx.x * 128 + t;
    int og = lin & 3;                         // 8 oc per thread
    int ics = ICS ? ((lin >> 2) & 1) : 0;
    int idx = ICS ? (lin >> 3) : (lin >> 2);
    int pp = idx % PPW;
    int tmp = idx / PPW;
    int py = tmp % HOUT;
    int b = tmp / HOUT;
    int cx0 = 4 * pp, cy0 = 2 * py;

    u64 acc[8][4];
#pragma unroll
    for (int i = 0; i < 8; i++)
#pragma unroll
        for (int p = 0; p < 4; p++) acc[i][p] = 0ULL;

    int icBeg = ICS ? ics * 4 : 0;
    int icEnd = icBeg + (ICS ? 4 : 8);
    for (int ic4 = icBeg; ic4 < icEnd; ic4++) {
#pragma unroll
        for (int iy = 0; iy < 4; iy++) {
            int gy = cy0 - 1 + iy;
            bool rowok = (unsigned)gy < (unsigned)HIN;
            float4 rowv[6];
#pragma unroll
            for (int c = 0; c < 6; c++) {
                int gx = cx0 - 1 + c;
                if (rowok && (unsigned)gx < (unsigned)HIN)
                    rowv[c] = reinterpret_cast<const float4*>(
                        in + ((size_t)(b * HIN + gy) * HIN + gx) * 32)[ic4];
                else
                    rowv[c] = make_float4(0.f, 0.f, 0.f, 0.f);
            }
#pragma unroll
            for (int s = 0; s < 4; s++) {
                u64 pu[6];
#pragma unroll
                for (int c = 0; c < 6; c++) pu[c] = pack2b(f4c(rowv[c], s));
#pragma unroll
                for (int r = 0; r < 2; r++) {
                    int ky = iy - r;
                    if (ky < 0 || ky > 2) continue;
#pragma unroll
                    for (int kx = 0; kx < 3; kx++) {
                        const ulonglong2* wp =
                            reinterpret_cast<const ulonglong2*>(
                                sw + (ky * 3 + kx) * 1024 + (ic4 * 4 + s) * 32 +
                                og * 8);
                        ulonglong2 wa = wp[0], wb = wp[1];
#pragma unroll
                        for (int c = 0; c < 4; c++) {
                            u64 v = pu[c + kx];
                            ffma2(acc[r * 4 + c][0], v, wa.x);
                            ffma2(acc[r * 4 + c][1], v, wa.y);
                            ffma2(acc[r * 4 + c][2], v, wb.x);
                            ffma2(acc[r * 4 + c][3], v, wb.y);
                        }
                    }
                }
            }
        }
    }

    if (ICS) {                                // combine ic halves (lane ^4)
#pragma unroll
        for (int i = 0; i < 8; i++)
#pragma unroll
            for (int p = 0; p < 4; p++)
                acc[i][p] = add2(acc[i][p],
                                 __shfl_xor_sync(0xffffffffu, acc[i][p], 4));
    }

    if (!ICS || ics == 0) {
#pragma unroll
        for (int cc = 0; cc < 2; cc++) {
            u64 resv[4];
#pragma unroll
            for (int p = 0; p < 4; p++) {
                float2 f00 = unpack2(acc[2 * cc][p]);
                float2 f01 = unpack2(acc[2 * cc + 1][p]);
                float2 f10 = unpack2(acc[4 + 2 * cc][p]);
                float2 f11 = unpack2(acc[4 + 2 * cc + 1][p]);
                float lo = lrelu(f00.x * BN_SCALE) + lrelu(f01.x * BN_SCALE) +
                           lrelu(f10.x * BN_SCALE) + lrelu(f11.x * BN_SCALE);
                float hi = lrelu(f00.y * BN_SCALE) + lrelu(f01.y * BN_SCALE) +
                           lrelu(f10.y * BN_SCALE) + lrelu(f11.y * BN_SCALE);
                resv[p] = pack2f(lo * 0.25f, hi * 0.25f);
            }
            int px = 2 * pp + cc;
            ulonglong2* op = reinterpret_cast<ulonglong2*>(
                out + ((size_t)(b * HOUT + py) * HOUT + px) * 32 + og * 8);
            op[0] = make_ulonglong2(resv[0], resv[1]);
            op[1] = make_ulonglong2(resv[2], resv[3]);
        }
    }
}

__global__ __launch_bounds__(128) void k_stage2(const float* __restrict__ w) {
    convpool_body<256, 0>(g_a1, g_a2, w);
}
__global__ __launch_bounds__(128) void k_stage3(const float* __restrict__ w) {
    convpool_body<128, 1>(g_a2, g_a3, w);
}

// ======== conv3x3 32->32 + BN + LReLU (64x64), 4px x 4oc x icsplit ========
__device__ __forceinline__ void fconv_body(const float* __restrict__ in,
                                           float* __restrict__ out,
                                           const float* __restrict__ w) {
    __shared__ float sw[9216];
    int t = threadIdx.x;
    for (int i = t; i < 9216; i += 128) sw[i] = w[i];
    __syncthreads();

    int lin = blockIdx.x * 128 + t;           // 65536 threads
    int og = lin & 7;                         // 4 oc each
    int ics = (lin >> 3) & 1;                 // ic half
    int idx = lin >> 4;
    int xb = idx & 15;                        // 4 px each
    int y = (idx >> 4) & 63;
    int b = idx >> 10;
    int x0 = 4 * xb;

    u64 acc[4][2];
#pragma unroll
    for (int c = 0; c < 4; c++) { acc[c][0] = 0ULL; acc[c][1] = 0ULL; }

    for (int ic4 = ics * 4; ic4 < ics * 4 + 4; ic4++) {
#pragma unroll
        for (int ky = 0; ky < 3; ky++) {
            int gy = y + ky - 1;
            bool rowok = (unsigned)gy < 64u;
            float4 rowv[6];
#pragma unroll
            for (int c = 0; c < 6; c++) {
                int gx = x0 - 1 + c;
                if (rowok && (unsigned)gx < 64u)
                    rowv[c] = reinterpret_cast<const float4*>(
                        in + ((size_t)((b * 64 + gy) * 64 + gx)) * 32)[ic4];
                else
                    rowv[c] = make_float4(0.f, 0.f, 0.f, 0.f);
            }
#pragma unroll
            for (int s = 0; s < 4; s++) {
                u64 pu[6];
#pragma unroll
                for (int c = 0; c < 6; c++) pu[c] = pack2b(f4c(rowv[c], s));
#pragma unroll
                for (int kx = 0; kx < 3; kx++) {
                    const ulonglong2* wp = reinterpret_cast<const ulonglong2*>(
                        sw + (ky * 3 + kx) * 1024 + (ic4 * 4 + s) * 32 + og * 4);
                    ulonglong2 wv = wp[0];
#pragma unroll
                    for (int c = 0; c < 4; c++) {
                        u64 v = pu[c + kx];
                        ffma2(acc[c][0], v, wv.x);
                        ffma2(acc[c][1], v, wv.y);
                    }
                }
            }
        }
    }

    // combine ic halves (lane ^8)
#pragma unroll
    for (int c = 0; c < 4; c++) {
        acc[c][0] = add2(acc[c][0], __shfl_xor_sync(0xffffffffu, acc[c][0], 8));
        acc[c][1] = add2(acc[c][1], __shfl_xor_sync(0xffffffffu, acc[c][1], 8));
    }

    if (ics == 0) {
#pragma unroll
        for (int c = 0; c < 4; c++) {
            float2 f0 = unpack2(acc[c][0]);
            float2 f1 = unpack2(acc[c][1]);
            float4 r;
            r.x = lrelu(f0.x * BN_SCALE);
            r.y = lrelu(f0.y * BN_SCALE);
            r.z = lrelu(f1.x * BN_SCALE);
            r.w = lrelu(f1.y * BN_SCALE);
            int pxl = (b * 64 + y) * 64 + x0 + c;
            reinterpret_cast<float4*>(out + (size_t)pxl * 32 + og * 4)[0] = r;
        }
    }
}

__global__ __launch_bounds__(128) void k_fconv0(const float* __restrict__ w) {
    fconv_body(g_a3, g_f0, w);
}
__global__ __launch_bounds__(128) void k_fconv1(const float* __restrict__ w) {
    fconv_body(g_f0, g_f1, w);
}

// ---------------- pointwise pw0 (LReLU) then pw1 -> disp ------------------
__global__ __launch_bounds__(128) void k_pw(const float* __restrict__ pw0,
                                            const float* __restrict__ pw1) {
    __shared__ float s0[1024];
    __shared__ float s1[64];
    int t = threadIdx.x;
    for (int i = t; i < 1024; i += 128) s0[i] = pw0[i];
    if (t < 64) s1[t] = pw1[t];
    __syncthreads();

    int idx = blockIdx.x * 128 + t;           // 16384
    const float4* ip = reinterpret_cast<const float4*>(g_f1 + (size_t)idx * 32);
    float xv[32];
#pragma unroll
    for (int i = 0; i < 8; i++) {
        float4 v = ip[i];
        xv[i * 4 + 0] = v.x; xv[i * 4 + 1] = v.y;
        xv[i * 4 + 2] = v.z; xv[i * 4 + 3] = v.w;
    }
    float d0 = 0.f, d1 = 0.f;
#pragma unroll
    for (int oc = 0; oc < 32; oc++) {
        float a = 0.f;
#pragma unroll
        for (int ic = 0; ic < 32; ic++) a += xv[ic] * s0[ic * 32 + oc];
        a = lrelu(a);
        d0 += a * s1[oc * 2 + 0];
        d1 += a * s1[oc * 2 + 1];
    }
    g_disp[idx * 2 + 0] = d0;
    g_disp[idx * 2 + 1] = d1;
}

// ---------------- B-spline upsample + bilinear warp + outputs -------------
__global__ __launch_bounds__(256) void k_warp(const float* __restrict__ moving,
                                              float* __restrict__ out) {
    int idx = blockIdx.x * 256 + threadIdx.x; // 4*512*512
    int b = idx >> 18;
    int rem = idx & 262143;
    int h = rem >> 9, w = rem & 511;

    float xv = fminf(w * 0.125f, 63.f);
    float yv = fminf(h * 0.125f, 63.f);
    int ii = (int)xv;
    int jj = (int)yv;
    float u = xv * 0.015625f;
    float v = yv * 0.015625f;

    float u2 = u * u, u3 = u2 * u;
    float v2 = v * v, v3 = v2 * v;
    float Bu[4] = { -u3 + 3.f * u2 - 3.f * u + 1.f,
                     3.f * u3 - 6.f * u2 + 4.f,
                    -3.f * u3 + 3.f * u2 + 3.f * u + 1.f,
                     u3 };
    float Bv[4] = { -v3 + 3.f * v2 - 3.f * v + 1.f,
                     3.f * v3 - 6.f * v2 + 4.f,
                    -3.f * v3 + 3.f * v2 + 3.f * v + 1.f,
                     v3 };

    const float2* dp = reinterpret_cast<const float2*>(g_disp);
    float i0 = 0.f, i1 = 0.f;
#pragma unroll
    for (int m = 0; m < 4; m++) {
        int ry = jj + m - 1;
        if ((unsigned)ry >= 64u) continue;
        float s0 = 0.f, s1 = 0.f;
#pragma unroll
        for (int n = 0; n < 4; n++) {
            int rx = ii + n - 1;
            if ((unsigned)rx >= 64u) continue;
            float2 d = dp[(b * 64 + ry) * 64 + rx];
            s0 += Bv[n] * d.x;
            s1 += Bv[n] * d.y;
        }
        i0 += Bu[m] * s0;
        i1 += Bu[m] * s1;
    }

    float wxf = i0 + (float)w;
    float wyf = i1 + (float)h;

    float fx = floorf(wxf);
    float x0 = fminf(fmaxf(fx, 0.f), 511.f);
    float x1 = fminf(fmaxf(fx + 1.f, 0.f), 511.f);
    float fy = floorf(wyf);
    float y0 = fminf(fmaxf(fy, 0.f), 511.f);
    float y1 = fminf(fmaxf(fy + 1.f, 0.f), 511.f);
    int x0i = (int)x0, x1i = (int)x1, y0i = (int)y0, y1i = (int)y1;

    const float* im = moving + ((size_t)b << 18);
    float Q1 = im[y0i * 512 + x0i];
    float Q2 = im[y1i * 512 + x0i];
    float Q3 = im[y0i * 512 + x1i];
    float Q4 = im[y1i * 512 + x1i];

    float invx = 1.f / (x1 - x0 + 1e-5f);
    float wxr = (x1 - wxf) * invx;
    float wxl = (wxf - x0) * invx;
    float R1 = wxr * Q1 + wxl * Q3;
    float R2 = wxr * Q2 + wxl * Q4;
    float invy = 1.f / (y1 - y0 + 1e-5f);
    float res = (y1 - wyf) * invy * R1 + (wyf - y0) * invy * R2;

    out[(b << 18) + (h << 9) + w] = res;
    const int WOFF = 4 * 512 * 512;
    out[WOFF + ((b * 2 + 0) << 18) + (h << 9) + w] = wxf;
    out[WOFF + ((b * 2 + 1) << 18) + (h << 9) + w] = wyf;
}

// ---------------- launch ---------------------------------------------------
extern "C" void kernel_launch(void* const* d_in, const int* in_sizes, int n_in,
                              void* d_out, int out_size) {
    const float* fixed  = (const float*)d_in[0];
    const float* moving = (const float*)d_in[1];
    const float* w0  = (const float*)d_in[2];
    const float* w1  = (const float*)d_in[3];
    const float* w2  = (const float*)d_in[4];
    const float* fw0 = (const float*)d_in[5];
    const float* fw1 = (const float*)d_in[6];
    const float* pw0 = (const float*)d_in[7];
    const float* pw1 = (const float*)d_in[8];
    float* out = (float*)d_out;

    k_conv0<<<4096, 128>>>(fixed, moving, w0);   // 512 -> 256, 8px x 8oc
    k_stage2<<<1024, 128>>>(w1);                 // 256 -> 128, 8px x 8oc
    k_stage3<<<512, 128>>>(w2);                  // 128 -> 64, 8px x 8oc x ics
    k_fconv0<<<512, 128>>>(fw0);                 // 64x64, 4px x 4oc x ics
    k_fconv1<<<512, 128>>>(fw1);                 // 64x64, 4px x 4oc x ics
    k_pw<<<128, 128>>>(pw0, pw1);                // pointwise -> disp
    k_warp<<<4096, 256>>>(moving, out);          // upsample + warp
}

// round 14
// speedup vs baseline: 1.6460x; 1.5561x over previous
#include <cuda_runtime.h>
#include <math.h>

#define ALPHA 0.2f
#define BN_SCALE 0.99950037f   // 1/sqrt(1 + 1e-3)

typedef unsigned long long u64;
typedef unsigned int u32;

// ---------------- packed f32x2 helpers ------------------------------------
__device__ __forceinline__ u64 pack2b(float v) {
    u64 r; asm("mov.b64 %0, {%1, %1};" : "=l"(r) : "f"(v)); return r;
}
__device__ __forceinline__ u64 pack2f(float lo, float hi) {
    u64 r; asm("mov.b64 %0, {%1, %2};" : "=l"(r) : "f"(lo), "f"(hi)); return r;
}
__device__ __forceinline__ float2 unpack2(u64 v) {
    float2 r; asm("mov.b64 {%0, %1}, %2;" : "=f"(r.x), "=f"(r.y) : "l"(v));
    return r;
}
__device__ __forceinline__ void ffma2(u64& d, u64 a, u64 b) {
    asm("fma.rn.f32x2 %0, %1, %2, %0;" : "+l"(d) : "l"(a), "l"(b));
}
__device__ __forceinline__ float lrelu(float x) {
    return x > 0.f ? x : ALPHA * x;
}
__device__ __forceinline__ u32 cvt_tf32(float f) {
    u32 r; asm("cvt.rna.tf32.f32 %0, %1;" : "=r"(r) : "f"(f)); return r;
}
__device__ __forceinline__ void mma_tf32(float c[4], u32 a0, u32 a1, u32 a2,
                                         u32 a3, u32 b0, u32 b1) {
    asm("mma.sync.aligned.m16n8k8.row.col.f32.tf32.tf32.f32 "
        "{%0,%1,%2,%3},{%4,%5,%6,%7},{%8,%9},{%0,%1,%2,%3};"
        : "+f"(c[0]), "+f"(c[1]), "+f"(c[2]), "+f"(c[3])
        : "r"(a0), "r"(a1), "r"(a2), "r"(a3), "r"(b0), "r"(b1));
}

// ---------------- scratch (device globals; no allocation) ----------------
__device__ float g_a1[4 * 256 * 256 * 32];
__device__ float g_a2[4 * 128 * 128 * 32];
__device__ float g_a3[4 * 64 * 64 * 32];
__device__ float g_f0[4 * 64 * 64 * 32];
__device__ float g_f1[4 * 64 * 64 * 32];
__device__ float g_disp[4 * 64 * 64 * 2];

// ============ stage 1: conv3x3 Cin=2 + BN + LReLU + pool, 8px x 8oc =======
__global__ __launch_bounds__(128) void k_conv0(const float* __restrict__ fixed,
                                               const float* __restrict__ moving,
                                               const float* __restrict__ w0) {
    __shared__ float sw[576];                 // (3,3,2,32)
    int t = threadIdx.x;
    for (int i = t; i < 576; i += 128) sw[i] = w0[i];
    __syncthreads();

    int lin = blockIdx.x * 128 + t;
    int og = lin & 3;
    int idx = lin >> 2;
    int pp = idx & 127;
    int py = (idx >> 7) & 255;
    int b = idx >> 15;
    int cx0 = 4 * pp, cy0 = 2 * py;

    u64 acc[8][4];
#pragma unroll
    for (int i = 0; i < 8; i++)
#pragma unroll
        for (int p = 0; p < 4; p++) acc[i][p] = 0ULL;

#pragma unroll
    for (int iy = 0; iy < 4; iy++) {
        int gy = cy0 - 1 + iy;
        bool rowok = (unsigned)gy < 512u;
        u64 pf[6], pm[6];
#pragma unroll
        for (int c = 0; c < 6; c++) {
            int gx = cx0 - 1 + c;
            bool ok = rowok && (unsigned)gx < 512u;
            int off = (b << 18) + (gy << 9) + gx;
            pf[c] = ok ? pack2b(fixed[off]) : 0ULL;
            pm[c] = ok ? pack2b(moving[off]) : 0ULL;
        }
#pragma unroll
        for (int r = 0; r < 2; r++) {
            int ky = iy - r;
            if (ky < 0 || ky > 2) continue;
#pragma unroll
            for (int kx = 0; kx < 3; kx++) {
                const ulonglong2* wf = reinterpret_cast<const ulonglong2*>(
                    sw + (ky * 3 + kx) * 64 + og * 8);
                const ulonglong2* wm = reinterpret_cast<const ulonglong2*>(
                    sw + (ky * 3 + kx) * 64 + 32 + og * 8);
                ulonglong2 wfa = wf[0], wfb = wf[1];
                ulonglong2 wma = wm[0], wmb = wm[1];
#pragma unroll
                for (int c = 0; c < 4; c++) {
                    u64 vf = pf[c + kx], vm = pm[c + kx];
                    ffma2(acc[r * 4 + c][0], vf, wfa.x);
                    ffma2(acc[r * 4 + c][1], vf, wfa.y);
                    ffma2(acc[r * 4 + c][2], vf, wfb.x);
                    ffma2(acc[r * 4 + c][3], vf, wfb.y);
                    ffma2(acc[r * 4 + c][0], vm, wma.x);
                    ffma2(acc[r * 4 + c][1], vm, wma.y);
                    ffma2(acc[r * 4 + c][2], vm, wmb.x);
                    ffma2(acc[r * 4 + c][3], vm, wmb.y);
                }
            }
        }
    }

#pragma unroll
    for (int cc = 0; cc < 2; cc++) {
        u64 resv[4];
#pragma unroll
        for (int p = 0; p < 4; p++) {
            float2 f00 = unpack2(acc[2 * cc][p]);
            float2 f01 = unpack2(acc[2 * cc + 1][p]);
            float2 f10 = unpack2(acc[4 + 2 * cc][p]);
            float2 f11 = unpack2(acc[4 + 2 * cc + 1][p]);
            float lo = lrelu(f00.x * BN_SCALE) + lrelu(f01.x * BN_SCALE) +
                       lrelu(f10.x * BN_SCALE) + lrelu(f11.x * BN_SCALE);
            float hi = lrelu(f00.y * BN_SCALE) + lrelu(f01.y * BN_SCALE) +
                       lrelu(f10.y * BN_SCALE) + lrelu(f11.y * BN_SCALE);
            resv[p] = pack2f(lo * 0.25f, hi * 0.25f);
        }
        int px = 2 * pp + cc;
        ulonglong2* op = reinterpret_cast<ulonglong2*>(
            g_a1 + ((size_t)(b * 256 + py) * 256 + px) * 32 + og * 8);
        op[0] = make_ulonglong2(resv[0], resv[1]);
        op[1] = make_ulonglong2(resv[2], resv[3]);
    }
}

// ============ tf32 tensor-core conv3x3 32->32 (+BN+LReLU, opt pool) =======
// Block: 128 thr = 4 warps; tile = 16x16 output px. Warp w owns rows 4w..4w+3
// (each image row = one m16 GEMM row-block along x), N=32 = 4 n8 groups.
// smem: input tile 18x18x32 tf32 (x-pitch 36 words -> conflict-free A frags),
// weights 9x32x32 tf32 (ic-pitch 36).
#define TPX 36
#define TPY 648
#define TILE_W 11664
#define WPIC 36
#define WPTAP 1152
#define TC_SMEM_BYTES ((TILE_W + 9 * WPIC * 32 / 32 * 32) * 0 + (11664 + 10368) * 4)

template <int HIN, int POOL>
__device__ __forceinline__ void conv_tc_body(const float* __restrict__ in,
                                             float* __restrict__ out,
                                             const float* __restrict__ w) {
    extern __shared__ u32 smem_u[];
    u32* tileS = smem_u;                      // 11664 words
    u32* WS = smem_u + TILE_W;                // 10368 words

    int t = threadIdx.x;
    int bid = blockIdx.x;
    const int TPB = HIN / 16;
    int tx = bid % TPB;
    int tmp = bid / TPB;
    int ty = tmp % TPB;
    int b = tmp / TPB;
    int gx0 = tx * 16 - 1, gy0 = ty * 16 - 1;

    // weights -> smem (tf32), layout [tap][ic*36 + oc]
    for (int i = t * 4; i < 9216; i += 512) {
        float4 v = *reinterpret_cast<const float4*>(w + i);
        int tap = i >> 10;
        int rem = i & 1023;
        int ic = rem >> 5, oc = rem & 31;
        u32* dst = WS + tap * WPTAP + ic * WPIC + oc;
        uint4 pv = make_uint4(cvt_tf32(v.x), cvt_tf32(v.y), cvt_tf32(v.z),
                              cvt_tf32(v.w));
        *reinterpret_cast<uint4*>(dst) = pv;
    }
    // input tile (18x18 px halo) -> smem (tf32)
    for (int i = t; i < 18 * 18 * 8; i += 128) {
        int ic4 = i & 7;
        int px = i >> 3;
        int xx = px % 18, yy = px / 18;
        int gy = gy0 + yy, gx = gx0 + xx;
        float4 v = make_float4(0.f, 0.f, 0.f, 0.f);
        if ((unsigned)gy < (unsigned)HIN && (unsigned)gx < (unsigned)HIN)
            v = *reinterpret_cast<const float4*>(
                in + ((size_t)(b * HIN + gy) * HIN + gx) * 32 + ic4 * 4);
        u32* dst = tileS + yy * TPY + xx * TPX + ic4 * 4;
        uint4 pv = make_uint4(cvt_tf32(v.x), cvt_tf32(v.y), cvt_tf32(v.z),
                              cvt_tf32(v.w));
        *reinterpret_cast<uint4*>(dst) = pv;
    }
    __syncthreads();

    int warp = t >> 5, lane = t & 31;
    int grp = lane >> 2, t4 = lane & 3;

    float c[4][4][4];                         // [row][ng][frag]
#pragma unroll
    for (int r = 0; r < 4; r++)
#pragma unroll
        for (int ng = 0; ng < 4; ng++)
#pragma unroll
            for (int j = 0; j < 4; j++) c[r][ng][j] = 0.f;

#pragma unroll
    for (int ky = 0; ky < 3; ky++) {
#pragma unroll
        for (int kx = 0; kx < 3; kx++) {
            const u32* Wt = WS + (ky * 3 + kx) * WPTAP;
#pragma unroll
            for (int s = 0; s < 4; s++) {
                u32 bf[4][2];
#pragma unroll
                for (int ng = 0; ng < 4; ng++) {
                    int oc = ng * 8 + grp;
                    bf[ng][0] = Wt[(8 * s + t4) * WPIC + oc];
                    bf[ng][1] = Wt[(8 * s + t4 + 4) * WPIC + oc];
                }
#pragma unroll
                for (int r = 0; r < 4; r++) {
                    const u32* Trow =
                        tileS + (warp * 4 + r + ky) * TPY + 8 * s + t4;
                    u32 a0 = Trow[(grp + kx) * TPX];
                    u32 a1 = Trow[(grp + 8 + kx) * TPX];
                    u32 a2 = Trow[(grp + kx) * TPX + 4];
                    u32 a3 = Trow[(grp + 8 + kx) * TPX + 4];
#pragma unroll
                    for (int ng = 0; ng < 4; ng++)
                        mma_tf32(c[r][ng], a0, a1, a2, a3, bf[ng][0],
                                 bf[ng][1]);
                }
            }
        }
    }

    if (POOL) {
        const int HOUT = HIN / 2;
#pragma unroll
        for (int rp = 0; rp < 2; rp++) {
#pragma unroll
            for (int ng = 0; ng < 4; ng++) {
                float p[4];
#pragma unroll
                for (int j = 0; j < 4; j++) {
                    p[j] = lrelu(c[2 * rp][ng][j] * BN_SCALE) +
                           lrelu(c[2 * rp + 1][ng][j] * BN_SCALE);
                }
#pragma unroll
                for (int j = 0; j < 4; j++)
                    p[j] += __shfl_xor_sync(0xffffffffu, p[j], 4);
                if ((grp & 1) == 0) {
                    int yh = ty * 8 + warp * 2 + rp;
                    int xh = tx * 8 + (grp >> 1);
                    int oc = ng * 8 + 2 * t4;
                    u64* o1 = reinterpret_cast<u64*>(
                        out + ((size_t)(b * HOUT + yh) * HOUT + xh) * 32 + oc);
                    *o1 = pack2f(p[0] * 0.25f, p[1] * 0.25f);
                    u64* o2 = reinterpret_cast<u64*>(
                        out + ((size_t)(b * HOUT + yh) * HOUT + xh + 4) * 32 +
                        oc);
                    *o2 = pack2f(p[2] * 0.25f, p[3] * 0.25f);
                }
            }
        }
    } else {
#pragma unroll
        for (int r = 0; r < 4; r++) {
            int y = ty * 16 + warp * 4 + r;
#pragma unroll
            for (int ng = 0; ng < 4; ng++) {
                int oc = ng * 8 + 2 * t4;
                int x0 = tx * 16 + grp;
                u64* o1 = reinterpret_cast<u64*>(
                    out + ((size_t)(b * HIN + y) * HIN + x0) * 32 + oc);
                *o1 = pack2f(lrelu(c[r][ng][0] * BN_SCALE),
                             lrelu(c[r][ng][1] * BN_SCALE));
                u64* o2 = reinterpret_cast<u64*>(
                    out + ((size_t)(b * HIN + y) * HIN + x0 + 8) * 32 + oc);
                *o2 = pack2f(lrelu(c[r][ng][2] * BN_SCALE),
                             lrelu(c[r][ng][3] * BN_SCALE));
            }
        }
    }
}

__global__ __launch_bounds__(128) void k_stage2(const float* __restrict__ w) {
    conv_tc_body<256, 1>(g_a1, g_a2, w);
}
__global__ __launch_bounds__(128) void k_stage3(const float* __restrict__ w) {
    conv_tc_body<128, 1>(g_a2, g_a3, w);
}
__global__ __launch_bounds__(128) void k_fconv0(const float* __restrict__ w) {
    conv_tc_body<64, 0>(g_a3, g_f0, w);
}
__global__ __launch_bounds__(128) void k_fconv1(const float* __restrict__ w) {
    conv_tc_body<64, 0>(g_f0, g_f1, w);
}

// ---------------- pointwise pw0 (LReLU) then pw1 -> disp ------------------
__global__ __launch_bounds__(128) void k_pw(const float* __restrict__ pw0,
                                            const float* __restrict__ pw1) {
    __shared__ float s0[1024];
    __shared__ float s1[64];
    int t = threadIdx.x;
    for (int i = t; i < 1024; i += 128) s0[i] = pw0[i];
    if (t < 64) s1[t] = pw1[t];
    __syncthreads();

    int idx = blockIdx.x * 128 + t;
    const float4* ip = reinterpret_cast<const float4*>(g_f1 + (size_t)idx * 32);
    float xv[32];
#pragma unroll
    for (int i = 0; i < 8; i++) {
        float4 v = ip[i];
        xv[i * 4 + 0] = v.x; xv[i * 4 + 1] = v.y;
        xv[i * 4 + 2] = v.z; xv[i * 4 + 3] = v.w;
    }
    float d0 = 0.f, d1 = 0.f;
#pragma unroll
    for (int oc = 0; oc < 32; oc++) {
        float a = 0.f;
#pragma unroll
        for (int ic = 0; ic < 32; ic++) a += xv[ic] * s0[ic * 32 + oc];
        a = lrelu(a);
        d0 += a * s1[oc * 2 + 0];
        d1 += a * s1[oc * 2 + 1];
    }
    g_disp[idx * 2 + 0] = d0;
    g_disp[idx * 2 + 1] = d1;
}

// ---------------- B-spline upsample + bilinear warp + outputs -------------
__global__ __launch_bounds__(256) void k_warp(const float* __restrict__ moving,
                                              float* __restrict__ out) {
    int idx = blockIdx.x * 256 + threadIdx.x;
    int b = idx >> 18;
    int rem = idx & 262143;
    int h = rem >> 9, w = rem & 511;

    float xv = fminf(w * 0.125f, 63.f);
    float yv = fminf(h * 0.125f, 63.f);
    int ii = (int)xv;
    int jj = (int)yv;
    float u = xv * 0.015625f;
    float v = yv * 0.015625f;

    float u2 = u * u, u3 = u2 * u;
    float v2 = v * v, v3 = v2 * v;
    float Bu[4] = { -u3 + 3.f * u2 - 3.f * u + 1.f,
                     3.f * u3 - 6.f * u2 + 4.f,
                    -3.f * u3 + 3.f * u2 + 3.f * u + 1.f,
                     u3 };
    float Bv[4] = { -v3 + 3.f * v2 - 3.f * v + 1.f,
                     3.f * v3 - 6.f * v2 + 4.f,
                    -3.f * v3 + 3.f * v2 + 3.f * v + 1.f,
                     v3 };

    const float2* dp = reinterpret_cast<const float2*>(g_disp);
    float i0 = 0.f, i1 = 0.f;
#pragma unroll
    for (int m = 0; m < 4; m++) {
        int ry = jj + m - 1;
        if ((unsigned)ry >= 64u) continue;
        float s0 = 0.f, s1 = 0.f;
#pragma unroll
        for (int n = 0; n < 4; n++) {
            int rx = ii + n - 1;
            if ((unsigned)rx >= 64u) continue;
            float2 d = dp[(b * 64 + ry) * 64 + rx];
            s0 += Bv[n] * d.x;
            s1 += Bv[n] * d.y;
        }
        i0 += Bu[m] * s0;
        i1 += Bu[m] * s1;
    }

    float wxf = i0 + (float)w;
    float wyf = i1 + (float)h;

    float fx = floorf(wxf);
    float x0 = fminf(fmaxf(fx, 0.f), 511.f);
    float x1 = fminf(fmaxf(fx + 1.f, 0.f), 511.f);
    float fy = floorf(wyf);
    float y0 = fminf(fmaxf(fy, 0.f), 511.f);
    float y1 = fminf(fmaxf(fy + 1.f, 0.f), 511.f);
    int x0i = (int)x0, x1i = (int)x1, y0i = (int)y0, y1i = (int)y1;

    const float* im = moving + ((size_t)b << 18);
    float Q1 = im[y0i * 512 + x0i];
    float Q2 = im[y1i * 512 + x0i];
    float Q3 = im[y0i * 512 + x1i];
    float Q4 = im[y1i * 512 + x1i];

    float invx = 1.f / (x1 - x0 + 1e-5f);
    float wxr = (x1 - wxf) * invx;
    float wxl = (wxf - x0) * invx;
    float R1 = wxr * Q1 + wxl * Q3;
    float R2 = wxr * Q2 + wxl * Q4;
    float invy = 1.f / (y1 - y0 + 1e-5f);
    float res = (y1 - wyf) * invy * R1 + (wyf - y0) * invy * R2;

    out[(b << 18) + (h << 9) + w] = res;
    const int WOFF = 4 * 512 * 512;
    out[WOFF + ((b * 2 + 0) << 18) + (h << 9) + w] = wxf;
    out[WOFF + ((b * 2 + 1) << 18) + (h << 9) + w] = wyf;
}

// ---------------- launch ---------------------------------------------------
extern "C" void kernel_launch(void* const* d_in, const int* in_sizes, int n_in,
                              void* d_out, int out_size) {
    const float* fixed  = (const float*)d_in[0];
    const float* moving = (const float*)d_in[1];
    const float* w0  = (const float*)d_in[2];
    const float* w1  = (const float*)d_in[3];
    const float* w2  = (const float*)d_in[4];
    const float* fw0 = (const float*)d_in[5];
    const float* fw1 = (const float*)d_in[6];
    const float* pw0 = (const float*)d_in[7];
    const float* pw1 = (const float*)d_in[8];
    float* out = (float*)d_out;

    const int SMEM = (11664 + 10368) * 4;     // 88128 B dynamic smem
    static bool attr_done = false;
    if (!attr_done) {
        cudaFuncSetAttribute(k_stage2, cudaFuncAttributeMaxDynamicSharedMemorySize, SMEM);
        cudaFuncSetAttribute(k_stage3, cudaFuncAttributeMaxDynamicSharedMemorySize, SMEM);
        cudaFuncSetAttribute(k_fconv0, cudaFuncAttributeMaxDynamicSharedMemorySize, SMEM);
        cudaFuncSetAttribute(k_fconv1, cudaFuncAttributeMaxDynamicSharedMemorySize, SMEM);
        attr_done = true;
    }

    k_conv0<<<4096, 128>>>(fixed, moving, w0);       // 512 -> 256 scalar
    k_stage2<<<1024, 128, SMEM>>>(w1);               // 256 -> 128 tf32 mma
    k_stage3<<<256, 128, SMEM>>>(w2);                // 128 -> 64  tf32 mma
    k_fconv0<<<64, 128, SMEM>>>(fw0);                // 64x64 tf32 mma
    k_fconv1<<<64, 128, SMEM>>>(fw1);                // 64x64 tf32 mma
    k_pw<<<128, 128>>>(pw0, pw1);                    // pointwise -> disp
    k_warp<<<4096, 256>>>(moving, out);              // upsample + warp
}

// round 15
// speedup vs baseline: 1.7270x; 1.0492x over previous
#include <cuda_runtime.h>
#include <math.h>

#define ALPHA 0.2f
#define BN_SCALE 0.99950037f   // 1/sqrt(1 + 1e-3)

typedef unsigned long long u64;
typedef unsigned int u32;

// ---------------- packed f32x2 helpers ------------------------------------
__device__ __forceinline__ u64 pack2b(float v) {
    u64 r; asm("mov.b64 %0, {%1, %1};" : "=l"(r) : "f"(v)); return r;
}
__device__ __forceinline__ u64 pack2f(float lo, float hi) {
    u64 r; asm("mov.b64 %0, {%1, %2};" : "=l"(r) : "f"(lo), "f"(hi)); return r;
}
__device__ __forceinline__ float2 unpack2(u64 v) {
    float2 r; asm("mov.b64 {%0, %1}, %2;" : "=f"(r.x), "=f"(r.y) : "l"(v));
    return r;
}
__device__ __forceinline__ void ffma2(u64& d, u64 a, u64 b) {
    asm("fma.rn.f32x2 %0, %1, %2, %0;" : "+l"(d) : "l"(a), "l"(b));
}
__device__ __forceinline__ float lrelu(float x) {
    return x > 0.f ? x : ALPHA * x;
}
__device__ __forceinline__ u32 cvt_tf32(float f) {
    u32 r; asm("cvt.rna.tf32.f32 %0, %1;" : "=r"(r) : "f"(f)); return r;
}
__device__ __forceinline__ void mma_tf32(float c[4], u32 a0, u32 a1, u32 a2,
                                         u32 a3, u32 b0, u32 b1) {
    asm("mma.sync.aligned.m16n8k8.row.col.f32.tf32.tf32.f32 "
        "{%0,%1,%2,%3},{%4,%5,%6,%7},{%8,%9},{%0,%1,%2,%3};"
        : "+f"(c[0]), "+f"(c[1]), "+f"(c[2]), "+f"(c[3])
        : "r"(a0), "r"(a1), "r"(a2), "r"(a3), "r"(b0), "r"(b1));
}

// ---------------- scratch (device globals; no allocation) ----------------
__device__ float g_a1[4 * 256 * 256 * 32];
__device__ float g_a2[4 * 128 * 128 * 32];
__device__ float g_a3[4 * 64 * 64 * 32];
__device__ float g_f0[4 * 64 * 64 * 32];
__device__ float g_f1[4 * 64 * 64 * 32];
__device__ float g_disp[4 * 64 * 64 * 2];

// ============ stage 1: conv3x3 Cin=2 + BN + LReLU + pool, 8px x 8oc =======
__global__ __launch_bounds__(128) void k_conv0(const float* __restrict__ fixed,
                                               const float* __restrict__ moving,
                                               const float* __restrict__ w0) {
    __shared__ float sw[576];                 // (3,3,2,32)
    int t = threadIdx.x;
    for (int i = t; i < 576; i += 128) sw[i] = w0[i];
    __syncthreads();

    int lin = blockIdx.x * 128 + t;
    int og = lin & 3;
    int idx = lin >> 2;
    int pp = idx & 127;
    int py = (idx >> 7) & 255;
    int b = idx >> 15;
    int cx0 = 4 * pp, cy0 = 2 * py;

    u64 acc[8][4];
#pragma unroll
    for (int i = 0; i < 8; i++)
#pragma unroll
        for (int p = 0; p < 4; p++) acc[i][p] = 0ULL;

#pragma unroll
    for (int iy = 0; iy < 4; iy++) {
        int gy = cy0 - 1 + iy;
        bool rowok = (unsigned)gy < 512u;
        u64 pf[6], pm[6];
#pragma unroll
        for (int c = 0; c < 6; c++) {
            int gx = cx0 - 1 + c;
            bool ok = rowok && (unsigned)gx < 512u;
            int off = (b << 18) + (gy << 9) + gx;
            pf[c] = ok ? pack2b(fixed[off]) : 0ULL;
            pm[c] = ok ? pack2b(moving[off]) : 0ULL;
        }
#pragma unroll
        for (int r = 0; r < 2; r++) {
            int ky = iy - r;
            if (ky < 0 || ky > 2) continue;
#pragma unroll
            for (int kx = 0; kx < 3; kx++) {
                const ulonglong2* wf = reinterpret_cast<const ulonglong2*>(
                    sw + (ky * 3 + kx) * 64 + og * 8);
                const ulonglong2* wm = reinterpret_cast<const ulonglong2*>(
                    sw + (ky * 3 + kx) * 64 + 32 + og * 8);
                ulonglong2 wfa = wf[0], wfb = wf[1];
                ulonglong2 wma = wm[0], wmb = wm[1];
#pragma unroll
                for (int c = 0; c < 4; c++) {
                    u64 vf = pf[c + kx], vm = pm[c + kx];
                    ffma2(acc[r * 4 + c][0], vf, wfa.x);
                    ffma2(acc[r * 4 + c][1], vf, wfa.y);
                    ffma2(acc[r * 4 + c][2], vf, wfb.x);
                    ffma2(acc[r * 4 + c][3], vf, wfb.y);
                    ffma2(acc[r * 4 + c][0], vm, wma.x);
                    ffma2(acc[r * 4 + c][1], vm, wma.y);
                    ffma2(acc[r * 4 + c][2], vm, wmb.x);
                    ffma2(acc[r * 4 + c][3], vm, wmb.y);
                }
            }
        }
    }

#pragma unroll
    for (int cc = 0; cc < 2; cc++) {
        u64 resv[4];
#pragma unroll
        for (int p = 0; p < 4; p++) {
            float2 f00 = unpack2(acc[2 * cc][p]);
            float2 f01 = unpack2(acc[2 * cc + 1][p]);
            float2 f10 = unpack2(acc[4 + 2 * cc][p]);
            float2 f11 = unpack2(acc[4 + 2 * cc + 1][p]);
            float lo = lrelu(f00.x * BN_SCALE) + lrelu(f01.x * BN_SCALE) +
                       lrelu(f10.x * BN_SCALE) + lrelu(f11.x * BN_SCALE);
            float hi = lrelu(f00.y * BN_SCALE) + lrelu(f01.y * BN_SCALE) +
                       lrelu(f10.y * BN_SCALE) + lrelu(f11.y * BN_SCALE);
            resv[p] = pack2f(lo * 0.25f, hi * 0.25f);
        }
        int px = 2 * pp + cc;
        ulonglong2* op = reinterpret_cast<ulonglong2*>(
            g_a1 + ((size_t)(b * 256 + py) * 256 + px) * 32 + og * 8);
        op[0] = make_ulonglong2(resv[0], resv[1]);
        op[1] = make_ulonglong2(resv[2], resv[3]);
    }
}

// ============ tf32 tensor-core conv3x3 32->32 (+BN+LReLU, opt pool) =======
// Block = 4 warps; tile = 16 wide x (4*RPW) tall. Warp w owns rows
// w*RPW..w*RPW+RPW-1. N=32 = 4 n8 groups.
#define TPX 36
#define TPY 648
#define WPIC 36
#define WPTAP 1152
#define W_WORDS 10368

template <int HIN, int POOL, int RPW>
__device__ __forceinline__ void conv_tc_body(const float* __restrict__ in,
                                             float* __restrict__ out,
                                             const float* __restrict__ w) {
    const int TH = 4 * RPW;                   // tile height
    const int HALO = TH + 2;
    extern __shared__ u32 smem_u[];
    u32* tileS = smem_u;                      // HALO*648 words
    u32* WS = smem_u + HALO * TPY;            // 10368 words

    int t = threadIdx.x;
    int bid = blockIdx.x;
    const int TPB_X = HIN / 16;
    const int TPB_Y = HIN / TH;
    int tx = bid % TPB_X;
    int tmp = bid / TPB_X;
    int ty = tmp % TPB_Y;
    int b = tmp / TPB_Y;
    int gx0 = tx * 16 - 1, gy0 = ty * TH - 1;

    // weights -> smem (tf32), layout [tap][ic*36 + oc]
    for (int i = t * 4; i < 9216; i += 512) {
        float4 v = *reinterpret_cast<const float4*>(w + i);
        int tap = i >> 10;
        int rem = i & 1023;
        int ic = rem >> 5, oc = rem & 31;
        u32* dst = WS + tap * WPTAP + ic * WPIC + oc;
        uint4 pv = make_uint4(cvt_tf32(v.x), cvt_tf32(v.y), cvt_tf32(v.z),
                              cvt_tf32(v.w));
        *reinterpret_cast<uint4*>(dst) = pv;
    }
    // input tile (HALO x 18 px) -> smem (tf32)
    for (int i = t; i < HALO * 18 * 8; i += 128) {
        int ic4 = i & 7;
        int px = i >> 3;
        int xx = px % 18, yy = px / 18;
        int gy = gy0 + yy, gx = gx0 + xx;
        float4 v = make_float4(0.f, 0.f, 0.f, 0.f);
        if ((unsigned)gy < (unsigned)HIN && (unsigned)gx < (unsigned)HIN)
            v = *reinterpret_cast<const float4*>(
                in + ((size_t)(b * HIN + gy) * HIN + gx) * 32 + ic4 * 4);
        u32* dst = tileS + yy * TPY + xx * TPX + ic4 * 4;
        uint4 pv = make_uint4(cvt_tf32(v.x), cvt_tf32(v.y), cvt_tf32(v.z),
                              cvt_tf32(v.w));
        *reinterpret_cast<uint4*>(dst) = pv;
    }
    __syncthreads();

    int warp = t >> 5, lane = t & 31;
    int grp = lane >> 2, t4 = lane & 3;

    float c[RPW][4][4];                       // [row][ng][frag]
#pragma unroll
    for (int r = 0; r < RPW; r++)
#pragma unroll
        for (int ng = 0; ng < 4; ng++)
#pragma unroll
            for (int j = 0; j < 4; j++) c[r][ng][j] = 0.f;

#pragma unroll
    for (int ky = 0; ky < 3; ky++) {
#pragma unroll
        for (int kx = 0; kx < 3; kx++) {
            const u32* Wt = WS + (ky * 3 + kx) * WPTAP;
#pragma unroll
            for (int s = 0; s < 4; s++) {
                u32 bf[4][2];
#pragma unroll
                for (int ng = 0; ng < 4; ng++) {
                    int oc = ng * 8 + grp;
                    bf[ng][0] = Wt[(8 * s + t4) * WPIC + oc];
                    bf[ng][1] = Wt[(8 * s + t4 + 4) * WPIC + oc];
                }
#pragma unroll
                for (int r = 0; r < RPW; r++) {
                    const u32* Trow =
                        tileS + (warp * RPW + r + ky) * TPY + 8 * s + t4;
                    u32 a0 = Trow[(grp + kx) * TPX];
                    u32 a1 = Trow[(grp + 8 + kx) * TPX];
                    u32 a2 = Trow[(grp + kx) * TPX + 4];
                    u32 a3 = Trow[(grp + 8 + kx) * TPX + 4];
#pragma unroll
                    for (int ng = 0; ng < 4; ng++)
                        mma_tf32(c[r][ng], a0, a1, a2, a3, bf[ng][0],
                                 bf[ng][1]);
                }
            }
        }
    }

    if (POOL) {
        const int HOUT = HIN / 2;
#pragma unroll
        for (int rp = 0; rp < RPW / 2; rp++) {
#pragma unroll
            for (int ng = 0; ng < 4; ng++) {
                float p[4];
#pragma unroll
                for (int j = 0; j < 4; j++) {
                    p[j] = lrelu(c[2 * rp][ng][j] * BN_SCALE) +
                           lrelu(c[2 * rp + 1][ng][j] * BN_SCALE);
                }
#pragma unroll
                for (int j = 0; j < 4; j++)
                    p[j] += __shfl_xor_sync(0xffffffffu, p[j], 4);
                if ((grp & 1) == 0) {
                    int yh = ty * (TH / 2) + warp * (RPW / 2) + rp;
                    int xh = tx * 8 + (grp >> 1);
                    int oc = ng * 8 + 2 * t4;
                    u64* o1 = reinterpret_cast<u64*>(
                        out + ((size_t)(b * HOUT + yh) * HOUT + xh) * 32 + oc);
                    *o1 = pack2f(p[0] * 0.25f, p[1] * 0.25f);
                    u64* o2 = reinterpret_cast<u64*>(
                        out + ((size_t)(b * HOUT + yh) * HOUT + xh + 4) * 32 +
                        oc);
                    *o2 = pack2f(p[2] * 0.25f, p[3] * 0.25f);
                }
            }
        }
    } else {
#pragma unroll
        for (int r = 0; r < RPW; r++) {
            int y = ty * TH + warp * RPW + r;
#pragma unroll
            for (int ng = 0; ng < 4; ng++) {
                int oc = ng * 8 + 2 * t4;
                int x0 = tx * 16 + grp;
                u64* o1 = reinterpret_cast<u64*>(
                    out + ((size_t)(b * HIN + y) * HIN + x0) * 32 + oc);
                *o1 = pack2f(lrelu(c[r][ng][0] * BN_SCALE),
                             lrelu(c[r][ng][1] * BN_SCALE));
                u64* o2 = reinterpret_cast<u64*>(
                    out + ((size_t)(b * HIN + y) * HIN + x0 + 8) * 32 + oc);
                *o2 = pack2f(lrelu(c[r][ng][2] * BN_SCALE),
                             lrelu(c[r][ng][3] * BN_SCALE));
            }
        }
    }
}

__global__ __launch_bounds__(128) void k_stage2(const float* __restrict__ w) {
    conv_tc_body<256, 1, 4>(g_a1, g_a2, w);
}
__global__ __launch_bounds__(128) void k_stage3(const float* __restrict__ w) {
    conv_tc_body<128, 1, 4>(g_a2, g_a3, w);
}
__global__ __launch_bounds__(128) void k_fconv0(const float* __restrict__ w) {
    conv_tc_body<64, 0, 1>(g_a3, g_f0, w);
}
__global__ __launch_bounds__(128) void k_fconv1(const float* __restrict__ w) {
    conv_tc_body<64, 0, 1>(g_f0, g_f1, w);
}

#define SMEM_BIG ((18 * 648 + 10368) * 4)     // RPW=4: 88128 B
#define SMEM_SMALL ((6 * 648 + 10368) * 4)    // RPW=1: 57024 B

// ---------------- pointwise pw0 (LReLU) then pw1 -> disp ------------------
__global__ __launch_bounds__(128) void k_pw(const float* __restrict__ pw0,
                                            const float* __restrict__ pw1) {
    __shared__ float s0[1024];
    __shared__ float s1[64];
    int t = threadIdx.x;
    for (int i = t; i < 1024; i += 128) s0[i] = pw0[i];
    if (t < 64) s1[t] = pw1[t];
    __syncthreads();

    int idx = blockIdx.x * 128 + t;
    const float4* ip = reinterpret_cast<const float4*>(g_f1 + (size_t)idx * 32);
    float xv[32];
#pragma unroll
    for (int i = 0; i < 8; i++) {
        float4 v = ip[i];
        xv[i * 4 + 0] = v.x; xv[i * 4 + 1] = v.y;
        xv[i * 4 + 2] = v.z; xv[i * 4 + 3] = v.w;
    }
    float d0 = 0.f, d1 = 0.f;
#pragma unroll
    for (int oc = 0; oc < 32; oc++) {
        float a = 0.f;
#pragma unroll
        for (int ic = 0; ic < 32; ic++) a += xv[ic] * s0[ic * 32 + oc];
        a = lrelu(a);
        d0 += a * s1[oc * 2 + 0];
        d1 += a * s1[oc * 2 + 1];
    }
    g_disp[idx * 2 + 0] = d0;
    g_disp[idx * 2 + 1] = d1;
}

// ---------------- B-spline upsample + bilinear warp + outputs -------------
__global__ __launch_bounds__(256) void k_warp(const float* __restrict__ moving,
                                              float* __restrict__ out) {
    int idx = blockIdx.x * 256 + threadIdx.x;
    int b = idx >> 18;
    int rem = idx & 262143;
    int h = rem >> 9, w = rem & 511;

    float xv = fminf(w * 0.125f, 63.f);
    float yv = fminf(h * 0.125f, 63.f);
    int ii = (int)xv;
    int jj = (int)yv;
    float u = xv * 0.015625f;
    float v = yv * 0.015625f;

    float u2 = u * u, u3 = u2 * u;
    float v2 = v * v, v3 = v2 * v;
    float Bu[4] = { -u3 + 3.f * u2 - 3.f * u + 1.f,
                     3.f * u3 - 6.f * u2 + 4.f,
                    -3.f * u3 + 3.f * u2 + 3.f * u + 1.f,
                     u3 };
    float Bv[4] = { -v3 + 3.f * v2 - 3.f * v + 1.f,
                     3.f * v3 - 6.f * v2 + 4.f,
                    -3.f * v3 + 3.f * v2 + 3.f * v + 1.f,
                     v3 };

    const float2* dp = reinterpret_cast<const float2*>(g_disp);
    float i0 = 0.f, i1 = 0.f;
#pragma unroll
    for (int m = 0; m < 4; m++) {
        int ry = jj + m - 1;
        if ((unsigned)ry >= 64u) continue;
        float s0 = 0.f, s1 = 0.f;
#pragma unroll
        for (int n = 0; n < 4; n++) {
            int rx = ii + n - 1;
            if ((unsigned)rx >= 64u) continue;
            float2 d = dp[(b * 64 + ry) * 64 + rx];
            s0 += Bv[n] * d.x;
            s1 += Bv[n] * d.y;
        }
        i0 += Bu[m] * s0;
        i1 += Bu[m] * s1;
    }

    float wxf = i0 + (float)w;
    float wyf = i1 + (float)h;

    float fx = floorf(wxf);
    float x0 = fminf(fmaxf(fx, 0.f), 511.f);
    float x1 = fminf(fmaxf(fx + 1.f, 0.f), 511.f);
    float fy = floorf(wyf);
    float y0 = fminf(fmaxf(fy, 0.f), 511.f);
    float y1 = fminf(fmaxf(fy + 1.f, 0.f), 511.f);
    int x0i = (int)x0, x1i = (int)x1, y0i = (int)y0, y1i = (int)y1;

    const float* im = moving + ((size_t)b << 18);
    float Q1 = im[y0i * 512 + x0i];
    float Q2 = im[y1i * 512 + x0i];
    float Q3 = im[y0i * 512 + x1i];
    float Q4 = im[y1i * 512 + x1i];

    float invx = 1.f / (x1 - x0 + 1e-5f);
    float wxr = (x1 - wxf) * invx;
    float wxl = (wxf - x0) * invx;
    float R1 = wxr * Q1 + wxl * Q3;
    float R2 = wxr * Q2 + wxl * Q4;
    float invy = 1.f / (y1 - y0 + 1e-5f);
    float res = (y1 - wyf) * invy * R1 + (wyf - y0) * invy * R2;

    out[(b << 18) + (h << 9) + w] = res;
    const int WOFF = 4 * 512 * 512;
    out[WOFF + ((b * 2 + 0) << 18) + (h << 9) + w] = wxf;
    out[WOFF + ((b * 2 + 1) << 18) + (h << 9) + w] = wyf;
}

// ---------------- launch ---------------------------------------------------
extern "C" void kernel_launch(void* const* d_in, const int* in_sizes, int n_in,
                              void* d_out, int out_size) {
    const float* fixed  = (const float*)d_in[0];
    const float* moving = (const float*)d_in[1];
    const float* w0  = (const float*)d_in[2];
    const float* w1  = (const float*)d_in[3];
    const float* w2  = (const float*)d_in[4];
    const float* fw0 = (const float*)d_in[5];
    const float* fw1 = (const float*)d_in[6];
    const float* pw0 = (const float*)d_in[7];
    const float* pw1 = (const float*)d_in[8];
    float* out = (float*)d_out;

    static bool attr_done = false;
    if (!attr_done) {
        cudaFuncSetAttribute(k_stage2, cudaFuncAttributeMaxDynamicSharedMemorySize, SMEM_BIG);
        cudaFuncSetAttribute(k_stage3, cudaFuncAttributeMaxDynamicSharedMemorySize, SMEM_BIG);
        cudaFuncSetAttribute(k_fconv0, cudaFuncAttributeMaxDynamicSharedMemorySize, SMEM_SMALL);
        cudaFuncSetAttribute(k_fconv1, cudaFuncAttributeMaxDynamicSharedMemorySize, SMEM_SMALL);
        attr_done = true;
    }

    k_conv0<<<4096, 128>>>(fixed, moving, w0);       // 512 -> 256 scalar
    k_stage2<<<1024, 128, SMEM_BIG>>>(w1);           // 256 -> 128 tf32 mma
    k_stage3<<<256, 128, SMEM_BIG>>>(w2);            // 128 -> 64  tf32 mma
    k_fconv0<<<256, 128, SMEM_SMALL>>>(fw0);         // 64x64 tf32, 16x4 tiles
    k_fconv1<<<256, 128, SMEM_SMALL>>>(fw1);         // 64x64 tf32, 16x4 tiles
    k_pw<<<128, 128>>>(pw0, pw1);                    // pointwise -> disp
    k_warp<<<4096, 256>>>(moving, out);              // upsample + warp
}